// round 4
// baseline (speedup 1.0000x reference)
#include <cuda_runtime.h>
#include <math.h>

// ---------------------------------------------------------------------------
// Scratch (static device globals; no runtime allocation)
// ---------------------------------------------------------------------------
// subbands  [sub][b][c][64][64]
__device__ float g_sb[4 * 8 * 64 * 64 * 64];
// conv outs [sub][b][co][64][64]
__device__ float g_co[4 * 8 * 64 * 64 * 64];
// per (b,c,sub) spatial sums
__device__ float g_sums[8 * 64 * 4];
// attention [b][sub][k]
__device__ float g_att[8 * 4 * 4];
// mixed kernels [b][sub][co][ci][3*3]
__device__ float g_mk[8 * 4 * 64 * 64 * 9];

#define SB_STRIDE  2097152   // 8*64*64*64 : one subband plane-set
#define NBC        512       // 8*64

// ---------------------------------------------------------------------------
// Kernel 1: Haar DWT (x -> 4 subbands) fused with per-(b,c) subband sums
// grid: 512 blocks (one per (b,c) plane), 256 threads
// ---------------------------------------------------------------------------
__global__ void dwt_kernel(const float* __restrict__ x) {
    int bc  = blockIdx.x;               // b*64 + c
    int tid = threadIdx.x;
    int ow  = tid & 63;
    int oh0 = tid >> 6;                 // 0..3
    const float* xp = x + (size_t)bc * 128 * 128;

    float s0 = 0.f, s1 = 0.f, s2 = 0.f, s3 = 0.f;
    #pragma unroll 4
    for (int it = 0; it < 16; ++it) {
        int oh = oh0 + it * 4;
        float2 t  = ((const float2*)(xp + (2 * oh)     * 128))[ow];
        float2 bo = ((const float2*)(xp + (2 * oh + 1) * 128))[ow];
        float a = t.x, b_ = t.y, c_ = bo.x, d_ = bo.y;
        float ll = (a + b_ + c_ + d_) * 0.5f;
        float h0 = (a + b_ - c_ - d_) * 0.5f;
        float h1 = (a - b_ + c_ - d_) * 0.5f;
        float hh = (a - b_ - c_ + d_) * 0.5f;
        int o = bc * 4096 + oh * 64 + ow;
        g_sb[0 * SB_STRIDE + o] = ll;
        g_sb[1 * SB_STRIDE + o] = h0;
        g_sb[2 * SB_STRIDE + o] = h1;
        g_sb[3 * SB_STRIDE + o] = hh;
        s0 += ll; s1 += h0; s2 += h1; s3 += hh;
    }

    // block reduction of the 4 sums
    #pragma unroll
    for (int off = 16; off; off >>= 1) {
        s0 += __shfl_down_sync(0xffffffffu, s0, off);
        s1 += __shfl_down_sync(0xffffffffu, s1, off);
        s2 += __shfl_down_sync(0xffffffffu, s2, off);
        s3 += __shfl_down_sync(0xffffffffu, s3, off);
    }
    __shared__ float red[8][4];
    int warp = tid >> 5, lane = tid & 31;
    if (lane == 0) {
        red[warp][0] = s0; red[warp][1] = s1;
        red[warp][2] = s2; red[warp][3] = s3;
    }
    __syncthreads();
    if (tid < 4) {
        float s = 0.f;
        #pragma unroll
        for (int w = 0; w < 8; ++w) s += red[w][tid];
        g_sums[bc * 4 + tid] = s;
    }
}

// ---------------------------------------------------------------------------
// Kernel 2a: attention logits + softmax. 1 block, 32 threads: one per (b,sub)
// ---------------------------------------------------------------------------
__global__ void attn_kernel(const float* __restrict__ attn_w,
                            const float* __restrict__ attn_b) {
    int t = threadIdx.x;
    if (t >= 32) return;
    int b = t >> 2, i = t & 3;
    float logits[4];
    #pragma unroll
    for (int k = 0; k < 4; ++k) {
        float acc = 0.f;
        for (int c = 0; c < 64; ++c)
            acc += attn_w[k * 64 + c] * g_sums[(b * 64 + c) * 4 + i];
        logits[k] = acc * (1.0f / 4096.0f) + attn_b[k];
    }
    float m = fmaxf(fmaxf(logits[0], logits[1]), fmaxf(logits[2], logits[3]));
    float e[4]; float s = 0.f;
    #pragma unroll
    for (int k = 0; k < 4; ++k) { e[k] = expf(logits[k] - m); s += e[k]; }
    float inv = 1.0f / s;
    #pragma unroll
    for (int k = 0; k < 4; ++k) g_att[(b * 4 + i) * 4 + k] = e[k] * inv;
}

// ---------------------------------------------------------------------------
// Kernel 2b: mixed kernels  mk[b,i,:] = sum_k att[b,i,k] * wt[k,i,:]
// Flat index trick: g_mk[b*147456 + inner] = sum_k wt[k*147456 + inner]
// ---------------------------------------------------------------------------
__global__ void mix_kernel(const float* __restrict__ wt) {
    int idx = blockIdx.x * blockDim.x + threadIdx.x;
    if (idx >= 8 * 147456) return;
    int b     = idx / 147456;
    int inner = idx - b * 147456;
    int i     = inner / 36864;      // 64*64*9
    const float* att = &g_att[(b * 4 + i) * 4];
    float a0 = att[0], a1 = att[1], a2 = att[2], a3 = att[3];
    float v = a0 * __ldg(&wt[inner])
            + a1 * __ldg(&wt[147456 + inner])
            + a2 * __ldg(&wt[2 * 147456 + inner])
            + a3 * __ldg(&wt[3 * 147456 + inner]);
    g_mk[idx] = v;
}

// ---------------------------------------------------------------------------
// Kernel 3: dynamic 3x3 conv, pad=1, per (b,sub).
// Block = 256 threads. Tile = all 64 cout x (8 rows x 16 cols).
// Thread = 4 cout x (2 rows x 4 cols) = 32 fp32 accumulators.
// smem: input halo tile 16ci x 10 x 18; weights [ci*9+uv][co] stride 65.
// ---------------------------------------------------------------------------
__global__ void __launch_bounds__(256, 2) conv_kernel() {
    int b    = blockIdx.z;
    int sub  = blockIdx.y;
    int tile = blockIdx.x;              // 0..31
    int th0  = (tile >> 2) << 3;        // tile row origin (8 rows)
    int tw0  = (tile & 3) << 4;         // tile col origin (16 cols)

    __shared__ float s_in[16 * 10 * 18];    // 11520 B
    __shared__ float s_w[144 * 65];         // 37440 B (total 48960 <= 48KB)

    int tid = threadIdx.x;
    int co4 = (tid >> 4) << 2;          // 0,4,...,60
    int sp  = tid & 15;
    int r0  = (sp >> 2) << 1;           // 0,2,4,6
    int c0  = (sp & 3) << 2;            // 0,4,8,12

    float acc[4][2][4];
    #pragma unroll
    for (int j = 0; j < 4; ++j)
        #pragma unroll
        for (int rr = 0; rr < 2; ++rr)
            #pragma unroll
            for (int cc = 0; cc < 4; ++cc) acc[j][rr][cc] = 0.f;

    const float* sbp = g_sb + (size_t)(sub * 8 + b) * 64 * 4096;   // [c][h][w]
    const float* mkp = g_mk + (size_t)(b * 4 + sub) * 36864;       // [co][ci][uv]

    for (int ci0 = 0; ci0 < 64; ci0 += 16) {
        __syncthreads();
        // ---- stage input halo tile (zero padded) ----
        for (int idx = tid; idx < 2880; idx += 256) {
            int ci  = idx / 180;
            int rem = idx - ci * 180;
            int y   = rem / 18;
            int xx  = rem - y * 18;
            int ih  = th0 - 1 + y;
            int iw  = tw0 - 1 + xx;
            float v = 0.f;
            if ((unsigned)ih < 64u && (unsigned)iw < 64u)
                v = sbp[(ci0 + ci) * 4096 + ih * 64 + iw];
            s_in[(ci * 10 + y) * 18 + xx] = v;
        }
        // ---- stage weights (transpose to [ci*9+uv][co], pad 65) ----
        for (int idx = tid; idx < 9216; idx += 256) {
            int co  = idx / 144;
            int rem = idx - co * 144;          // ci_local*9 + uv
            s_w[rem * 65 + co] = mkp[co * 576 + ci0 * 9 + rem];
        }
        __syncthreads();

        // ---- compute ----
        #pragma unroll 1
        for (int ci = 0; ci < 16; ++ci) {
            float inreg[4][6];
            const float* ibase = &s_in[(ci * 10 + r0) * 18 + c0];
            #pragma unroll
            for (int y = 0; y < 4; ++y)
                #pragma unroll
                for (int xx = 0; xx < 6; ++xx)
                    inreg[y][xx] = ibase[y * 18 + xx];

            const float* wbase = &s_w[ci * 9 * 65 + co4];
            #pragma unroll
            for (int u = 0; u < 3; ++u) {
                #pragma unroll
                for (int v = 0; v < 3; ++v) {
                    const float* wp = wbase + (u * 3 + v) * 65;
                    float w0 = wp[0], w1 = wp[1], w2 = wp[2], w3 = wp[3];
                    #pragma unroll
                    for (int rr = 0; rr < 2; ++rr) {
                        #pragma unroll
                        for (int cc = 0; cc < 4; ++cc) {
                            float iv = inreg[rr + u][cc + v];
                            acc[0][rr][cc] += w0 * iv;
                            acc[1][rr][cc] += w1 * iv;
                            acc[2][rr][cc] += w2 * iv;
                            acc[3][rr][cc] += w3 * iv;
                        }
                    }
                }
            }
        }
    }

    // ---- write conv outputs ----
    float* outp = g_co + (size_t)(sub * 8 + b) * 64 * 4096;
    #pragma unroll
    for (int j = 0; j < 4; ++j) {
        #pragma unroll
        for (int rr = 0; rr < 2; ++rr) {
            float4 v = make_float4(acc[j][rr][0], acc[j][rr][1],
                                   acc[j][rr][2], acc[j][rr][3]);
            *(float4*)(outp + (co4 + j) * 4096 + (th0 + r0 + rr) * 64
                       + (tw0 + c0)) = v;
        }
    }
}

// ---------------------------------------------------------------------------
// Kernel 4: inverse Haar DWT -> final output (8,64,128,128)
// ---------------------------------------------------------------------------
__global__ void idwt_kernel(float* __restrict__ out) {
    int idx = blockIdx.x * blockDim.x + threadIdx.x;   // over 2097152
    if (idx >= SB_STRIDE) return;
    int w  = idx & 63;
    int h  = (idx >> 6) & 63;
    int bc = idx >> 12;                                 // b*64 + c

    float ll = g_co[idx];
    float h0 = g_co[SB_STRIDE + idx];
    float h1 = g_co[2 * SB_STRIDE + idx];
    float hh = g_co[3 * SB_STRIDE + idx];

    float a  = (ll + h0 + h1 + hh) * 0.5f;
    float b_ = (ll + h0 - h1 - hh) * 0.5f;
    float c_ = (ll - h0 + h1 - hh) * 0.5f;
    float d_ = (ll - h0 - h1 + hh) * 0.5f;

    float2* top = (float2*)(out + ((size_t)bc * 128 + 2 * h) * 128);
    float2* bot = (float2*)(out + ((size_t)bc * 128 + 2 * h + 1) * 128);
    top[w] = make_float2(a, b_);
    bot[w] = make_float2(c_, d_);
}

// ---------------------------------------------------------------------------
// Launch
// ---------------------------------------------------------------------------
extern "C" void kernel_launch(void* const* d_in, const int* in_sizes, int n_in,
                              void* d_out, int out_size) {
    const float* x  = (const float*)d_in[0];   // (8,64,128,128)
    const float* wt = (const float*)d_in[1];   // (4,4,64,64,3,3)
    const float* aw = (const float*)d_in[2];   // (4,64)
    const float* ab = (const float*)d_in[3];   // (4,)
    float* out = (float*)d_out;

    dwt_kernel<<<NBC, 256>>>(x);
    attn_kernel<<<1, 32>>>(aw, ab);
    mix_kernel<<<4608, 256>>>(wt);
    dim3 cgrid(32, 4, 8);                      // (tile, sub, batch)
    conv_kernel<<<cgrid, 256>>>();
    idwt_kernel<<<8192, 256>>>(out);
}

// round 5
// speedup vs baseline: 1.3171x; 1.3171x over previous
#include <cuda_runtime.h>
#include <math.h>

// ---------------------------------------------------------------------------
// Scratch (static device globals; no runtime allocation)
// ---------------------------------------------------------------------------
// subbands  [sub][b][c][64][64]
__device__ float g_sb[4 * 8 * 64 * 64 * 64];
// conv outs [sub][b][co][64][64]
__device__ float g_co[4 * 8 * 64 * 64 * 64];
// per (b,c,sub) spatial sums
__device__ float g_sums[8 * 64 * 4];
// attention [b][sub][k]
__device__ float g_att[8 * 4 * 4];
// mixed kernels, TRANSPOSED layout: [b][sub][ci][uv][co]   (co contiguous)
__device__ float g_mk[8 * 4 * 64 * 9 * 64];

#define SB_STRIDE  2097152   // 8*64*64*64 : one subband plane-set
#define NBC        512       // 8*64

// ---------------------------------------------------------------------------
// Kernel 1: Haar DWT (x -> 4 subbands) fused with per-(b,c) subband sums
// ---------------------------------------------------------------------------
__global__ void dwt_kernel(const float* __restrict__ x) {
    int bc  = blockIdx.x;               // b*64 + c
    int tid = threadIdx.x;
    int ow  = tid & 63;
    int oh0 = tid >> 6;                 // 0..3
    const float* xp = x + (size_t)bc * 128 * 128;

    float s0 = 0.f, s1 = 0.f, s2 = 0.f, s3 = 0.f;
    #pragma unroll 4
    for (int it = 0; it < 16; ++it) {
        int oh = oh0 + it * 4;
        float2 t  = ((const float2*)(xp + (2 * oh)     * 128))[ow];
        float2 bo = ((const float2*)(xp + (2 * oh + 1) * 128))[ow];
        float a = t.x, b_ = t.y, c_ = bo.x, d_ = bo.y;
        float ll = (a + b_ + c_ + d_) * 0.5f;
        float h0 = (a + b_ - c_ - d_) * 0.5f;
        float h1 = (a - b_ + c_ - d_) * 0.5f;
        float hh = (a - b_ - c_ + d_) * 0.5f;
        int o = bc * 4096 + oh * 64 + ow;
        g_sb[0 * SB_STRIDE + o] = ll;
        g_sb[1 * SB_STRIDE + o] = h0;
        g_sb[2 * SB_STRIDE + o] = h1;
        g_sb[3 * SB_STRIDE + o] = hh;
        s0 += ll; s1 += h0; s2 += h1; s3 += hh;
    }

    #pragma unroll
    for (int off = 16; off; off >>= 1) {
        s0 += __shfl_down_sync(0xffffffffu, s0, off);
        s1 += __shfl_down_sync(0xffffffffu, s1, off);
        s2 += __shfl_down_sync(0xffffffffu, s2, off);
        s3 += __shfl_down_sync(0xffffffffu, s3, off);
    }
    __shared__ float red[8][4];
    int warp = tid >> 5, lane = tid & 31;
    if (lane == 0) {
        red[warp][0] = s0; red[warp][1] = s1;
        red[warp][2] = s2; red[warp][3] = s3;
    }
    __syncthreads();
    if (tid < 4) {
        float s = 0.f;
        #pragma unroll
        for (int w = 0; w < 8; ++w) s += red[w][tid];
        g_sums[bc * 4 + tid] = s;
    }
}

// ---------------------------------------------------------------------------
// Kernel 2a: attention logits + softmax. 1 block, 32 threads: one per (b,sub)
// ---------------------------------------------------------------------------
__global__ void attn_kernel(const float* __restrict__ attn_w,
                            const float* __restrict__ attn_b) {
    int t = threadIdx.x;
    if (t >= 32) return;
    int b = t >> 2, i = t & 3;
    float logits[4];
    #pragma unroll
    for (int k = 0; k < 4; ++k) {
        float acc = 0.f;
        for (int c = 0; c < 64; ++c)
            acc += attn_w[k * 64 + c] * g_sums[(b * 64 + c) * 4 + i];
        logits[k] = acc * (1.0f / 4096.0f) + attn_b[k];
    }
    float m = fmaxf(fmaxf(logits[0], logits[1]), fmaxf(logits[2], logits[3]));
    float e[4]; float s = 0.f;
    #pragma unroll
    for (int k = 0; k < 4; ++k) { e[k] = expf(logits[k] - m); s += e[k]; }
    float inv = 1.0f / s;
    #pragma unroll
    for (int k = 0; k < 4; ++k) g_att[(b * 4 + i) * 4 + k] = e[k] * inv;
}

// ---------------------------------------------------------------------------
// Kernel 2b: mixed kernels with TRANSPOSE.
//   g_mk[b][i][ci][uv][co] = sum_k att[b,i,k] * wt[k][i][co][ci][uv]
// Block handles (b, i, ci-group of 8). Per k: load 64co x 72(ci,uv) tile
// coalesced, transpose through padded smem, accumulate 18 outputs/thread.
// grid = 8*4*8 = 256 blocks, 256 threads.
// ---------------------------------------------------------------------------
__global__ void mix_kernel(const float* __restrict__ wt) {
    int blk = blockIdx.x;
    int ci0 = (blk & 7) * 8;            // 0,8,...,56
    int bi  = blk >> 3;                 // b*4 + i
    int b   = bi >> 2;
    int i   = bi & 3;

    __shared__ float s_t[72 * 65];      // [j= cil*9+uv][co], pad 65

    int tid = threadIdx.x;
    int co  = tid & 63;
    int j0  = tid >> 6;                 // 0..3 : handles j = j0, j0+4, ... (18 each)

    float acc[18];
    #pragma unroll
    for (int q = 0; q < 18; ++q) acc[q] = 0.f;

    #pragma unroll
    for (int k = 0; k < 4; ++k) {
        float ak = g_att[(b * 4 + i) * 4 + k];
        const float* src = wt + (((size_t)k * 4 + i) * 64) * 576 + ci0 * 9;
        __syncthreads();
        // load 64co x 72j coalesced, store transposed (pad 65: conflict-free)
        for (int idx = tid; idx < 64 * 72; idx += 256) {
            int c = idx / 72;
            int j = idx - c * 72;
            s_t[j * 65 + c] = src[(size_t)c * 576 + j];
        }
        __syncthreads();
        #pragma unroll
        for (int q = 0; q < 18; ++q) {
            int j = j0 + q * 4;
            acc[q] += ak * s_t[j * 65 + co];
        }
    }

    float* dst = g_mk + ((size_t)bi * 576 + ci0 * 9) * 64;
    #pragma unroll
    for (int q = 0; q < 18; ++q) {
        int j = j0 + q * 4;
        dst[j * 64 + co] = acc[q];      // coalesced over co
    }
}

// ---------------------------------------------------------------------------
// Kernel 3: dynamic 3x3 conv, pad=1, per (b,sub).  PACKED F32X2 version.
// Block = 256 threads. Tile = 64 cout x (8 rows x 16 cols).
// Thread = 4 cout x (2 rows x 4 cols) = 32 accumulators held as 16 f32x2.
// smem: input halo 16ci x 10 x 18; weights [ci*9+uv][co] (co contiguous).
// ---------------------------------------------------------------------------
__global__ void __launch_bounds__(256, 2) conv_kernel() {
    int b    = blockIdx.z;
    int sub  = blockIdx.y;
    int tile = blockIdx.x;              // 0..31
    int th0  = (tile >> 2) << 3;        // tile row origin (8 rows)
    int tw0  = (tile & 3) << 4;         // tile col origin (16 cols)

    __shared__ float s_in[16 * 10 * 18];    // 11520 B
    __shared__ float s_w[144 * 64];         // 36864 B  (total 48384 <= 48KB)

    int tid = threadIdx.x;
    int co4 = (tid >> 4) << 2;          // 0,4,...,60
    int sp  = tid & 15;
    int r0  = (sp >> 2) << 1;           // 0,2,4,6
    int c0  = (sp & 3) << 2;            // 0,4,8,12

    // acc01[rr][cc] packs couts (co4+0, co4+1); acc23 packs (co4+2, co4+3)
    unsigned long long acc01[2][4], acc23[2][4];
    #pragma unroll
    for (int rr = 0; rr < 2; ++rr)
        #pragma unroll
        for (int cc = 0; cc < 4; ++cc) { acc01[rr][cc] = 0ull; acc23[rr][cc] = 0ull; }

    const float* sbp = g_sb + (size_t)(sub * 8 + b) * 64 * 4096;   // [c][h][w]
    const float* mkp = g_mk + (size_t)(b * 4 + sub) * 36864;       // [ci][uv][co]

    for (int ci0 = 0; ci0 < 64; ci0 += 16) {
        __syncthreads();
        // ---- stage input halo tile (zero padded) ----
        for (int idx = tid; idx < 2880; idx += 256) {
            int ci  = idx / 180;
            int rem = idx - ci * 180;
            int y   = rem / 18;
            int xx  = rem - y * 18;
            int ih  = th0 - 1 + y;
            int iw  = tw0 - 1 + xx;
            float v = 0.f;
            if ((unsigned)ih < 64u && (unsigned)iw < 64u)
                v = sbp[(ci0 + ci) * 4096 + ih * 64 + iw];
            s_in[(ci * 10 + y) * 18 + xx] = v;
        }
        // ---- stage weights: straight float4 copy (coalesced, conflict-free)
        {
            const float4* src = (const float4*)(mkp + ci0 * 9 * 64);
            float4* dst = (float4*)s_w;
            for (int idx = tid; idx < 2304; idx += 256)
                dst[idx] = src[idx];
        }
        __syncthreads();

        // ---- compute ----
        #pragma unroll 1
        for (int ci = 0; ci < 16; ++ci) {
            // pack 4x6 input patch as broadcast f32x2
            unsigned long long iv2[4][6];
            const float* ibase = &s_in[(ci * 10 + r0) * 18 + c0];
            #pragma unroll
            for (int y = 0; y < 4; ++y)
                #pragma unroll
                for (int xx = 0; xx < 6; ++xx) {
                    float v = ibase[y * 18 + xx];
                    asm("mov.b64 %0, {%1, %1};" : "=l"(iv2[y][xx]) : "f"(v));
                }

            const float* wci = &s_w[ci * 9 * 64 + co4];
            #pragma unroll
            for (int u = 0; u < 3; ++u) {
                #pragma unroll
                for (int v = 0; v < 3; ++v) {
                    // 4 consecutive cout weights = two packed f32x2 operands
                    ulonglong2 w = *(const ulonglong2*)(wci + (u * 3 + v) * 64);
                    #pragma unroll
                    for (int rr = 0; rr < 2; ++rr) {
                        #pragma unroll
                        for (int cc = 0; cc < 4; ++cc) {
                            unsigned long long iv = iv2[rr + u][cc + v];
                            asm volatile("fma.rn.f32x2 %0, %1, %2, %0;"
                                         : "+l"(acc01[rr][cc])
                                         : "l"(w.x), "l"(iv));
                            asm volatile("fma.rn.f32x2 %0, %1, %2, %0;"
                                         : "+l"(acc23[rr][cc])
                                         : "l"(w.y), "l"(iv));
                        }
                    }
                }
            }
        }
    }

    // ---- unpack + write conv outputs (float4 per cout row) ----
    float* outp = g_co + (size_t)(sub * 8 + b) * 64 * 4096;
    #pragma unroll
    for (int rr = 0; rr < 2; ++rr) {
        float o0[4], o1[4], o2[4], o3[4];
        #pragma unroll
        for (int cc = 0; cc < 4; ++cc) {
            asm("mov.b64 {%0, %1}, %2;" : "=f"(o0[cc]), "=f"(o1[cc]) : "l"(acc01[rr][cc]));
            asm("mov.b64 {%0, %1}, %2;" : "=f"(o2[cc]), "=f"(o3[cc]) : "l"(acc23[rr][cc]));
        }
        size_t rowoff = (size_t)(th0 + r0 + rr) * 64 + (tw0 + c0);
        *(float4*)(outp + (size_t)(co4 + 0) * 4096 + rowoff) = make_float4(o0[0], o0[1], o0[2], o0[3]);
        *(float4*)(outp + (size_t)(co4 + 1) * 4096 + rowoff) = make_float4(o1[0], o1[1], o1[2], o1[3]);
        *(float4*)(outp + (size_t)(co4 + 2) * 4096 + rowoff) = make_float4(o2[0], o2[1], o2[2], o2[3]);
        *(float4*)(outp + (size_t)(co4 + 3) * 4096 + rowoff) = make_float4(o3[0], o3[1], o3[2], o3[3]);
    }
}

// ---------------------------------------------------------------------------
// Kernel 4: inverse Haar DWT -> final output (8,64,128,128)
// ---------------------------------------------------------------------------
__global__ void idwt_kernel(float* __restrict__ out) {
    int idx = blockIdx.x * blockDim.x + threadIdx.x;   // over 2097152
    if (idx >= SB_STRIDE) return;
    int w  = idx & 63;
    int h  = (idx >> 6) & 63;
    int bc = idx >> 12;                                 // b*64 + c

    float ll = g_co[idx];
    float h0 = g_co[SB_STRIDE + idx];
    float h1 = g_co[2 * SB_STRIDE + idx];
    float hh = g_co[3 * SB_STRIDE + idx];

    float a  = (ll + h0 + h1 + hh) * 0.5f;
    float b_ = (ll + h0 - h1 - hh) * 0.5f;
    float c_ = (ll - h0 + h1 - hh) * 0.5f;
    float d_ = (ll - h0 - h1 + hh) * 0.5f;

    float2* top = (float2*)(out + ((size_t)bc * 128 + 2 * h) * 128);
    float2* bot = (float2*)(out + ((size_t)bc * 128 + 2 * h + 1) * 128);
    top[w] = make_float2(a, b_);
    bot[w] = make_float2(c_, d_);
}

// ---------------------------------------------------------------------------
// Launch
// ---------------------------------------------------------------------------
extern "C" void kernel_launch(void* const* d_in, const int* in_sizes, int n_in,
                              void* d_out, int out_size) {
    const float* x  = (const float*)d_in[0];   // (8,64,128,128)
    const float* wt = (const float*)d_in[1];   // (4,4,64,64,3,3)
    const float* aw = (const float*)d_in[2];   // (4,64)
    const float* ab = (const float*)d_in[3];   // (4,)
    float* out = (float*)d_out;

    dwt_kernel<<<NBC, 256>>>(x);
    attn_kernel<<<1, 32>>>(aw, ab);
    mix_kernel<<<256, 256>>>(wt);
    dim3 cgrid(32, 4, 8);                      // (tile, sub, batch)
    conv_kernel<<<cgrid, 256>>>();
    idwt_kernel<<<8192, 256>>>(out);
}